// round 2
// baseline (speedup 1.0000x reference)
#include <cuda_runtime.h>
#include <cuda_bf16.h>
#include <cstdint>

// out[b,h] = sum_{d,m} x[b,d,m]*w1[m,h,d]*w2[h,d] + C[h]
//   b=256, d=2048, m=64, h=128  ->  one GEMM: M=256, N=128, K=131072
//   X[b,k] = x with k = d*64+m (already contiguous in memory)
//   U[h,k] = w1[m,h,d]*w2[h,d]  (precomputed, bf16 hi/lo split)
//   C[h]   = sum_d b1[h,d]*w2[h,d] + b2[h]
// GEMM via mma.sync m16n8k16 bf16 (base sm_103 ISA; tcgen05 not available
// because the harness PTX stage targets compute_103 without the 'a' feature).

static constexpr int Ddim = 2048;
static constexpr int Mhist = 64;
static constexpr int Hdim = 128;
static constexpr int KTOT = Ddim * Mhist;   // 131072

static constexpr int KSPLIT = 64;           // grid.x
static constexpr int KPC = KTOT / KSPLIT;   // 2048 K per CTA
static constexpr int KC = 64;               // K per chunk (bf16 cols, 128B row)
static constexpr int CHUNKS = KPC / KC;     // 32

// Device scratch (allocation-free rule: __device__ globals)
__device__ __nv_bfloat16 g_U_hi[(size_t)Hdim * KTOT];
__device__ __nv_bfloat16 g_U_lo[(size_t)Hdim * KTOT];
__device__ float g_C[Hdim];

__device__ __forceinline__ uint32_t smem_u32(const void* p) {
    uint32_t a;
    asm("{ .reg .u64 t; cvta.to.shared.u64 t, %1; cvt.u32.u64 %0, t; }" : "=r"(a) : "l"(p));
    return a;
}
__device__ __forceinline__ uint32_t sw128(uint32_t off) { return off ^ ((off >> 3) & 0x70); }
__device__ __forceinline__ uint32_t bf2_bits(__nv_bfloat162 v) {
    return reinterpret_cast<uint32_t&>(v);
}

__device__ __forceinline__ void ldsm_x4(uint32_t& r0, uint32_t& r1, uint32_t& r2, uint32_t& r3,
                                        uint32_t addr) {
    asm volatile("ldmatrix.sync.aligned.m8n8.x4.shared.b16 {%0,%1,%2,%3}, [%4];"
                 : "=r"(r0), "=r"(r1), "=r"(r2), "=r"(r3) : "r"(addr));
}
__device__ __forceinline__ void mma16816(float* c, const uint32_t* a, const uint32_t* b) {
    asm volatile(
        "mma.sync.aligned.m16n8k16.row.col.f32.bf16.bf16.f32 "
        "{%0,%1,%2,%3}, {%4,%5,%6,%7}, {%8,%9}, {%0,%1,%2,%3};"
        : "+f"(c[0]), "+f"(c[1]), "+f"(c[2]), "+f"(c[3])
        : "r"(a[0]), "r"(a[1]), "r"(a[2]), "r"(a[3]), "r"(b[0]), "r"(b[1]));
}

// ---------------- precompute kernels ----------------
// U[h][d*64+m] = w1[(m*128+h)*2048+d] * w2[h*2048+d], split into bf16 hi/lo.
__global__ void build_u_kernel(const float* __restrict__ w1, const float* __restrict__ w2) {
    int g = blockIdx.x * blockDim.x + threadIdx.x;      // 0 .. 128*2048-1
    int h = g >> 11;
    int d = g & 2047;
    float s = w2[h * Ddim + d];
    uint32_t hi[32], lo[32];
#pragma unroll 8
    for (int m = 0; m < Mhist; m += 2) {
        float a = w1[((size_t)m * Hdim + h) * Ddim + d] * s;
        float b = w1[((size_t)(m + 1) * Hdim + h) * Ddim + d] * s;
        __nv_bfloat162 H = __floats2bfloat162_rn(a, b);
        float la = a - __low2float(H);
        float lb = b - __high2float(H);
        __nv_bfloat162 L = __floats2bfloat162_rn(la, lb);
        hi[m >> 1] = bf2_bits(H);
        lo[m >> 1] = bf2_bits(L);
    }
    size_t base = (size_t)h * KTOT + (size_t)d * Mhist;   // 128B aligned
    uint4* ph = reinterpret_cast<uint4*>(g_U_hi + base);
    uint4* pl = reinterpret_cast<uint4*>(g_U_lo + base);
#pragma unroll
    for (int j = 0; j < 8; j++) {
        ph[j] = reinterpret_cast<uint4*>(hi)[j];
        pl[j] = reinterpret_cast<uint4*>(lo)[j];
    }
}

__global__ void bias_kernel(const float* __restrict__ b1, const float* __restrict__ w2,
                            const float* __restrict__ b2) {
    __shared__ float red[256];
    int h = blockIdx.x;
    float s = 0.0f;
    for (int d = threadIdx.x; d < Ddim; d += 256)
        s += b1[h * Ddim + d] * w2[h * Ddim + d];
    red[threadIdx.x] = s;
    __syncthreads();
    for (int st = 128; st > 0; st >>= 1) {
        if (threadIdx.x < st) red[threadIdx.x] += red[threadIdx.x + st];
        __syncthreads();
    }
    if (threadIdx.x == 0) g_C[h] = red[0] + b2[h];
}

// out[b][h] initialized with bias C[h] (runs after bias_kernel)
__global__ void init_out_kernel(float* out, int n) {
    int i = blockIdx.x * blockDim.x + threadIdx.x;
    if (i < n) out[i] = g_C[i & (Hdim - 1)];
}

// ---------------- GEMM kernel ----------------
// grid (KSPLIT=64, 2 M-tiles), 256 threads = 8 warps (2x4 warp grid),
// CTA tile 128x128, warp tile 64x32.
// smem: A_hi/A_lo/B_hi/B_lo tiles, each 128 rows x 64 bf16 (128B rows, SW128).
static constexpr int S_AHI = 0;
static constexpr int S_ALO = 16384;
static constexpr int S_BHI = 32768;
static constexpr int S_BLO = 49152;
static constexpr int SMEM_TOTAL = 65536;

__global__ void __launch_bounds__(256, 1)
gemm_kernel(const float* __restrict__ x, float* __restrict__ out) {
    extern __shared__ char smem[];
    uint32_t sb = smem_u32(smem);
    int tid = threadIdx.x;
    int wid = tid >> 5;
    int lane = tid & 31;
    int warp_m = wid >> 2;          // 0..1
    int warp_n = wid & 3;           // 0..3
    int ksp = blockIdx.x;
    int mtile = blockIdx.y;

    // ---- gmem pointers for this thread's load slice ----
    int arow = tid >> 1;            // A tile row 0..127
    int half = tid & 1;             // which 32-col half
    const float* xr = x + ((size_t)(mtile * 128 + arow)) * KTOT
                        + (size_t)ksp * KPC + half * 32;
    const __nv_bfloat16* uh = g_U_hi + (size_t)arow * KTOT + (size_t)ksp * KPC + half * 32;
    const __nv_bfloat16* ul = g_U_lo + (size_t)arow * KTOT + (size_t)ksp * KPC + half * 32;

    // ---- ldmatrix lane address components ----
    // A (row-major m x k): row = base + (lane&15), kbyte += (lane>>4)*16
    uint32_t a_row_l = (uint32_t)(warp_m * 64 + (lane & 15));
    uint32_t a_kb_l = (uint32_t)((lane >> 4) * 16);
    // B (n-major rows of k): n = base + ((lane>>4)<<3) + (lane&7), kbyte += ((lane>>3)&1)*16
    uint32_t b_row_l = (uint32_t)(warp_n * 32 + ((lane >> 4) << 3) + (lane & 7));
    uint32_t b_kb_l = (uint32_t)(((lane >> 3) & 1) * 16);

    float acc[4][4][4];
#pragma unroll
    for (int i = 0; i < 4; i++)
#pragma unroll
        for (int j = 0; j < 4; j++)
#pragma unroll
            for (int r = 0; r < 4; r++) acc[i][j][r] = 0.0f;

    // prefetch registers
    float4 xreg[8];
    uint4 uhreg[4], ulreg[4];

    // initial gmem fetch (chunk 0)
#pragma unroll
    for (int j = 0; j < 8; j++) xreg[j] = reinterpret_cast<const float4*>(xr)[j];
#pragma unroll
    for (int j = 0; j < 4; j++) {
        uhreg[j] = reinterpret_cast<const uint4*>(uh)[j];
        ulreg[j] = reinterpret_cast<const uint4*>(ul)[j];
    }

    for (int c = 0; c < CHUNKS; c++) {
        // ---- store current chunk regs -> smem (bf16 hi/lo, SW128) ----
#pragma unroll
        for (int j = 0; j < 8; j++) {
            float4 v = xreg[j];
            __nv_bfloat162 H01 = __floats2bfloat162_rn(v.x, v.y);
            __nv_bfloat162 H23 = __floats2bfloat162_rn(v.z, v.w);
            __nv_bfloat162 L01 = __floats2bfloat162_rn(v.x - __low2float(H01), v.y - __high2float(H01));
            __nv_bfloat162 L23 = __floats2bfloat162_rn(v.z - __low2float(H23), v.w - __high2float(H23));
            uint32_t off = sw128((uint32_t)(arow * 128 + half * 64 + j * 8));
            uint2 sh; sh.x = bf2_bits(H01); sh.y = bf2_bits(H23);
            uint2 sl; sl.x = bf2_bits(L01); sl.y = bf2_bits(L23);
            *reinterpret_cast<uint2*>(smem + S_AHI + off) = sh;
            *reinterpret_cast<uint2*>(smem + S_ALO + off) = sl;
        }
#pragma unroll
        for (int j = 0; j < 4; j++) {
            uint32_t off = sw128((uint32_t)(arow * 128 + half * 64 + j * 16));
            *reinterpret_cast<uint4*>(smem + S_BHI + off) = uhreg[j];
            *reinterpret_cast<uint4*>(smem + S_BLO + off) = ulreg[j];
        }
        __syncthreads();

        // ---- issue next chunk's gmem loads (latency hidden by MMA below) ----
        if (c + 1 < CHUNKS) {
            const float4* xp = reinterpret_cast<const float4*>(xr + (c + 1) * KC);
            const uint4* uhp = reinterpret_cast<const uint4*>(uh + (c + 1) * KC);
            const uint4* ulp = reinterpret_cast<const uint4*>(ul + (c + 1) * KC);
#pragma unroll
            for (int j = 0; j < 8; j++) xreg[j] = xp[j];
#pragma unroll
            for (int j = 0; j < 4; j++) { uhreg[j] = uhp[j]; ulreg[j] = ulp[j]; }
        }

        // ---- MMA: 3 products (hi*hi, hi*lo, lo*hi), 4 k16-steps each ----
#pragma unroll
        for (int p = 0; p < 3; p++) {
            uint32_t Abase = sb + ((p == 2) ? S_ALO : S_AHI);
            uint32_t Bbase = sb + ((p == 1) ? S_BLO : S_BHI);
#pragma unroll
            for (int ks = 0; ks < 4; ks++) {
                uint32_t bfr[4][2];
#pragma unroll
                for (int nf2 = 0; nf2 < 2; nf2++) {
                    uint32_t addr = Bbase + sw128((b_row_l + nf2 * 16) * 128 + ks * 32 + b_kb_l);
                    ldsm_x4(bfr[nf2 * 2][0], bfr[nf2 * 2][1],
                            bfr[nf2 * 2 + 1][0], bfr[nf2 * 2 + 1][1], addr);
                }
#pragma unroll
                for (int mf = 0; mf < 4; mf++) {
                    uint32_t afr[4];
                    uint32_t addr = Abase + sw128((a_row_l + mf * 16) * 128 + ks * 32 + a_kb_l);
                    ldsm_x4(afr[0], afr[1], afr[2], afr[3], addr);
#pragma unroll
                    for (int nf = 0; nf < 4; nf++)
                        mma16816(acc[mf][nf], afr, bfr[nf]);
                }
            }
        }
        __syncthreads();
    }

    // ---- epilogue: split-K reduce via atomics ----
    int r0 = mtile * 128 + warp_m * 64 + (lane >> 2);
    int c0 = warp_n * 32 + (lane & 3) * 2;
#pragma unroll
    for (int mf = 0; mf < 4; mf++) {
#pragma unroll
        for (int nf = 0; nf < 4; nf++) {
            int row = r0 + mf * 16;
            int col = c0 + nf * 8;
            atomicAdd(out + (size_t)row * Hdim + col,            acc[mf][nf][0]);
            atomicAdd(out + (size_t)row * Hdim + col + 1,        acc[mf][nf][1]);
            atomicAdd(out + (size_t)(row + 8) * Hdim + col,      acc[mf][nf][2]);
            atomicAdd(out + (size_t)(row + 8) * Hdim + col + 1,  acc[mf][nf][3]);
        }
    }
}

// ---------------- launch ----------------
extern "C" void kernel_launch(void* const* d_in, const int* in_sizes, int n_in,
                              void* d_out, int out_size) {
    const float* x  = (const float*)d_in[0];
    const float* w1 = (const float*)d_in[1];
    const float* b1 = (const float*)d_in[2];
    const float* w2 = (const float*)d_in[3];
    const float* b2 = (const float*)d_in[4];
    float* out = (float*)d_out;

    cudaFuncSetAttribute(gemm_kernel, cudaFuncAttributeMaxDynamicSharedMemorySize, SMEM_TOTAL);

    build_u_kernel<<<(Hdim * Ddim) / 256, 256>>>(w1, w2);
    bias_kernel<<<Hdim, 256>>>(b1, w2, b2);
    init_out_kernel<<<(out_size + 255) / 256, 256>>>(out, out_size);
    dim3 grid(KSPLIT, 2);
    gemm_kernel<<<grid, 256, SMEM_TOTAL>>>(x, out);
}

// round 3
// speedup vs baseline: 1.3274x; 1.3274x over previous
#include <cuda_runtime.h>
#include <cuda_bf16.h>
#include <cstdint>

// out[b,h] = sum_{d,m} x[b,d,m]*w1[m,h,d]*w2[h,d] + C[h]
//   -> one GEMM: M=256, N=128, K=131072 (k = d*64+m contiguous in x)
//   U[h,k] = w1*w2 precomputed bf16 hi/lo (Markidis 3-product split)
// mma.sync m16n8k16 bf16; tcgen05 unavailable (harness targets compute_103, no 'a').

static constexpr int Ddim = 2048;
static constexpr int Mhist = 64;
static constexpr int Hdim = 128;
static constexpr int KTOT = Ddim * Mhist;     // 131072
static constexpr int KC = 64;                  // K per chunk
static constexpr int NCHUNK = KTOT / KC;       // 2048
static constexpr int KSPLIT = 74;              // grid.x ; grid.y = 2 -> 148 CTAs

__device__ __nv_bfloat16 g_U_hi[(size_t)Hdim * KTOT];
__device__ __nv_bfloat16 g_U_lo[(size_t)Hdim * KTOT];
__device__ float g_C[Hdim];

__device__ __forceinline__ uint32_t smem_u32(const void* p) {
    uint32_t a;
    asm("{ .reg .u64 t; cvta.to.shared.u64 t, %1; cvt.u32.u64 %0, t; }" : "=r"(a) : "l"(p));
    return a;
}
__device__ __forceinline__ uint32_t sw128(uint32_t off) { return off ^ ((off >> 3) & 0x70); }
__device__ __forceinline__ uint32_t bf2_bits(__nv_bfloat162 v) {
    return reinterpret_cast<uint32_t&>(v);
}
__device__ __forceinline__ void ldsm_x4(uint32_t& r0, uint32_t& r1, uint32_t& r2, uint32_t& r3,
                                        uint32_t addr) {
    asm volatile("ldmatrix.sync.aligned.m8n8.x4.shared.b16 {%0,%1,%2,%3}, [%4];"
                 : "=r"(r0), "=r"(r1), "=r"(r2), "=r"(r3) : "r"(addr));
}
__device__ __forceinline__ void mma16816(float* c, const uint32_t* a, const uint32_t* b) {
    asm volatile(
        "mma.sync.aligned.m16n8k16.row.col.f32.bf16.bf16.f32 "
        "{%0,%1,%2,%3}, {%4,%5,%6,%7}, {%8,%9}, {%0,%1,%2,%3};"
        : "+f"(c[0]), "+f"(c[1]), "+f"(c[2]), "+f"(c[3])
        : "r"(a[0]), "r"(a[1]), "r"(a[2]), "r"(a[3]), "r"(b[0]), "r"(b[1]));
}
__device__ __forceinline__ void cp_async16(uint32_t dst, const void* src) {
    asm volatile("cp.async.cg.shared.global [%0], [%1], 16;" :: "r"(dst), "l"(src));
}
#define CP_COMMIT() asm volatile("cp.async.commit_group;" ::: "memory")
#define CP_WAIT_ALL() asm volatile("cp.async.wait_group 0;" ::: "memory")

// ---------------- precompute ----------------
__global__ void build_u_kernel(const float* __restrict__ w1, const float* __restrict__ w2) {
    int g = blockIdx.x * blockDim.x + threadIdx.x;  // 0 .. 128*2048-1
    int h = g >> 11;
    int d = g & 2047;
    float s = w2[h * Ddim + d];
    uint32_t hi[32], lo[32];
#pragma unroll 16
    for (int m = 0; m < Mhist; m += 2) {
        float a = w1[((size_t)m * Hdim + h) * Ddim + d] * s;
        float b = w1[((size_t)(m + 1) * Hdim + h) * Ddim + d] * s;
        __nv_bfloat162 H = __floats2bfloat162_rn(a, b);
        float la = a - __low2float(H);
        float lb = b - __high2float(H);
        __nv_bfloat162 L = __floats2bfloat162_rn(la, lb);
        hi[m >> 1] = bf2_bits(H);
        lo[m >> 1] = bf2_bits(L);
    }
    size_t base = (size_t)h * KTOT + (size_t)d * Mhist;
    uint4* ph = reinterpret_cast<uint4*>(g_U_hi + base);
    uint4* pl = reinterpret_cast<uint4*>(g_U_lo + base);
#pragma unroll
    for (int j = 0; j < 8; j++) {
        ph[j] = reinterpret_cast<uint4*>(hi)[j];
        pl[j] = reinterpret_cast<uint4*>(lo)[j];
    }
}

__global__ void bias_kernel(const float* __restrict__ b1, const float* __restrict__ w2,
                            const float* __restrict__ b2) {
    __shared__ float red[256];
    int h = blockIdx.x;
    float s = 0.0f;
    for (int d = threadIdx.x; d < Ddim; d += 256)
        s += b1[h * Ddim + d] * w2[h * Ddim + d];
    red[threadIdx.x] = s;
    __syncthreads();
    for (int st = 128; st > 0; st >>= 1) {
        if (threadIdx.x < st) red[threadIdx.x] += red[threadIdx.x + st];
        __syncthreads();
    }
    if (threadIdx.x == 0) g_C[h] = red[0] + b2[h];
}

__global__ void init_out_kernel(float* out, int n) {
    int i = blockIdx.x * blockDim.x + threadIdx.x;
    if (i < n) out[i] = g_C[i & (Hdim - 1)];
}

// ---------------- GEMM ----------------
// 256 threads = 8 warps (2x4), CTA tile 128x128, warp tile 64x32.
// Double-buffered smem: stage = {A_hi, A_lo, B_hi, B_lo} 16KB each = 64KB; 2 stages.
static constexpr int S_AHI = 0;
static constexpr int S_ALO = 16384;
static constexpr int S_BHI = 32768;
static constexpr int S_BLO = 49152;
static constexpr int STAGE = 65536;
static constexpr int SMEM_TOTAL = 2 * STAGE;   // 131072

__global__ void __launch_bounds__(256, 1)
gemm_kernel(const float* __restrict__ x, float* __restrict__ out) {
    extern __shared__ char smem[];
    uint32_t sb = smem_u32(smem);
    int tid = threadIdx.x;
    int wid = tid >> 5;
    int lane = tid & 31;
    int warp_m = wid >> 2;
    int warp_n = wid & 3;
    int ksp = blockIdx.x;
    int mtile = blockIdx.y;

    int c0 = (ksp * NCHUNK) / KSPLIT;
    int c1 = ((ksp + 1) * NCHUNK) / KSPLIT;

    int arow = tid >> 1;
    int half = tid & 1;
    const float* xr = x + ((size_t)(mtile * 128 + arow)) * KTOT + half * 32;
    const __nv_bfloat16* uh = g_U_hi + (size_t)arow * KTOT + half * 32;
    const __nv_bfloat16* ul = g_U_lo + (size_t)arow * KTOT + half * 32;

    // STS A base offsets (within stage), swizzled once
    uint32_t a_sts[8];
#pragma unroll
    for (int j = 0; j < 8; j++) a_sts[j] = sw128((uint32_t)(arow * 128 + half * 64 + j * 8));
    // cp.async B dst offsets (within stage)
    uint32_t b_dst[4];
#pragma unroll
    for (int j = 0; j < 4; j++) b_dst[j] = sw128((uint32_t)(arow * 128 + half * 64 + j * 16));

    // ldmatrix lane address components (validated in R2)
    uint32_t a_row_l = (uint32_t)(warp_m * 64 + (lane & 15));
    uint32_t a_kb_l = (uint32_t)((lane >> 4) * 16);
    uint32_t b_row_l = (uint32_t)(warp_n * 32 + ((lane >> 4) << 3) + (lane & 7));
    uint32_t b_kb_l = (uint32_t)(((lane >> 3) & 1) * 16);

    float acc[4][4][4];
#pragma unroll
    for (int i = 0; i < 4; i++)
#pragma unroll
        for (int j = 0; j < 4; j++)
#pragma unroll
            for (int r = 0; r < 4; r++) acc[i][j][r] = 0.0f;

    float4 xreg[8];

    // ---- prologue: chunk c0 ----
    {
        const float4* xp = reinterpret_cast<const float4*>(xr + c0 * KC);
#pragma unroll
        for (int j = 0; j < 8; j++) xreg[j] = xp[j];
        const __nv_bfloat16* uhp = uh + c0 * KC;
        const __nv_bfloat16* ulp = ul + c0 * KC;
#pragma unroll
        for (int j = 0; j < 4; j++) {
            cp_async16(sb + S_BHI + b_dst[j], uhp + j * 8);
            cp_async16(sb + S_BLO + b_dst[j], ulp + j * 8);
        }
        CP_COMMIT();
    }

    for (int c = c0; c < c1; c++) {
        uint32_t stg = (uint32_t)((c - c0) & 1) * STAGE;
        uint32_t nstg = stg ^ STAGE;

        // convert + store A(c) into current stage
#pragma unroll
        for (int j = 0; j < 8; j++) {
            float4 v = xreg[j];
            __nv_bfloat162 H01 = __floats2bfloat162_rn(v.x, v.y);
            __nv_bfloat162 H23 = __floats2bfloat162_rn(v.z, v.w);
            __nv_bfloat162 L01 = __floats2bfloat162_rn(v.x - __low2float(H01), v.y - __high2float(H01));
            __nv_bfloat162 L23 = __floats2bfloat162_rn(v.z - __low2float(H23), v.w - __high2float(H23));
            uint2 sh; sh.x = bf2_bits(H01); sh.y = bf2_bits(H23);
            uint2 sl; sl.x = bf2_bits(L01); sl.y = bf2_bits(L23);
            *reinterpret_cast<uint2*>(smem + stg + S_AHI + a_sts[j]) = sh;
            *reinterpret_cast<uint2*>(smem + stg + S_ALO + a_sts[j]) = sl;
        }
        CP_WAIT_ALL();           // B(c) landed
        __syncthreads();         // stage(c) fully visible; stage(c^1) readers done

        if (c + 1 < c1) {
            const float4* xp = reinterpret_cast<const float4*>(xr + (c + 1) * KC);
#pragma unroll
            for (int j = 0; j < 8; j++) xreg[j] = xp[j];
            const __nv_bfloat16* uhp = uh + (c + 1) * KC;
            const __nv_bfloat16* ulp = ul + (c + 1) * KC;
#pragma unroll
            for (int j = 0; j < 4; j++) {
                cp_async16(sb + nstg + S_BHI + b_dst[j], uhp + j * 8);
                cp_async16(sb + nstg + S_BLO + b_dst[j], ulp + j * 8);
            }
            CP_COMMIT();
        }

        // ---- MMA on stage(c): per k16-step load frags once, 3 products ----
        uint32_t Ahi = sb + stg + S_AHI, Alo = sb + stg + S_ALO;
        uint32_t Bhi = sb + stg + S_BHI, Blo = sb + stg + S_BLO;
#pragma unroll
        for (int ks = 0; ks < 4; ks++) {
            uint32_t bh[4][2], bl[4][2];
#pragma unroll
            for (int nf2 = 0; nf2 < 2; nf2++) {
                uint32_t off = sw128((b_row_l + nf2 * 16) * 128 + ks * 32 + b_kb_l);
                ldsm_x4(bh[nf2 * 2][0], bh[nf2 * 2][1], bh[nf2 * 2 + 1][0], bh[nf2 * 2 + 1][1], Bhi + off);
                ldsm_x4(bl[nf2 * 2][0], bl[nf2 * 2][1], bl[nf2 * 2 + 1][0], bl[nf2 * 2 + 1][1], Blo + off);
            }
#pragma unroll
            for (int mf = 0; mf < 4; mf++) {
                uint32_t off = sw128((a_row_l + mf * 16) * 128 + ks * 32 + a_kb_l);
                uint32_t ah[4], al[4];
                ldsm_x4(ah[0], ah[1], ah[2], ah[3], Ahi + off);
                ldsm_x4(al[0], al[1], al[2], al[3], Alo + off);
#pragma unroll
                for (int nf = 0; nf < 4; nf++) {
                    mma16816(acc[mf][nf], ah, bh[nf]);   // hi*hi
                    mma16816(acc[mf][nf], ah, bl[nf]);   // hi*lo
                    mma16816(acc[mf][nf], al, bh[nf]);   // lo*hi
                }
            }
        }
    }

    // ---- epilogue: split-K reduce via atomics (out pre-filled with bias) ----
    int r0 = mtile * 128 + warp_m * 64 + (lane >> 2);
    int cc0 = warp_n * 32 + (lane & 3) * 2;
#pragma unroll
    for (int mf = 0; mf < 4; mf++) {
#pragma unroll
        for (int nf = 0; nf < 4; nf++) {
            int row = r0 + mf * 16;
            int col = cc0 + nf * 8;
            atomicAdd(out + (size_t)row * Hdim + col,           acc[mf][nf][0]);
            atomicAdd(out + (size_t)row * Hdim + col + 1,       acc[mf][nf][1]);
            atomicAdd(out + (size_t)(row + 8) * Hdim + col,     acc[mf][nf][2]);
            atomicAdd(out + (size_t)(row + 8) * Hdim + col + 1, acc[mf][nf][3]);
        }
    }
}

// ---------------- launch ----------------
extern "C" void kernel_launch(void* const* d_in, const int* in_sizes, int n_in,
                              void* d_out, int out_size) {
    const float* x  = (const float*)d_in[0];
    const float* w1 = (const float*)d_in[1];
    const float* b1 = (const float*)d_in[2];
    const float* w2 = (const float*)d_in[3];
    const float* b2 = (const float*)d_in[4];
    float* out = (float*)d_out;

    cudaFuncSetAttribute(gemm_kernel, cudaFuncAttributeMaxDynamicSharedMemorySize, SMEM_TOTAL);

    build_u_kernel<<<(Hdim * Ddim) / 256, 256>>>(w1, w2);
    bias_kernel<<<Hdim, 256>>>(b1, w2, b2);
    init_out_kernel<<<(out_size + 255) / 256, 256>>>(out, out_size);
    dim3 grid(KSPLIT, 2);
    gemm_kernel<<<grid, 256, SMEM_TOTAL>>>(x, out);
}

// round 4
// speedup vs baseline: 1.7858x; 1.3453x over previous
#include <cuda_runtime.h>
#include <cuda_bf16.h>
#include <cstdint>

// out[b,h] = sum_{d,m} x[b,d,m]*w1[m,h,d]*w2[h,d] + C[h]
//   -> one GEMM: M=256, N=128, K=131072 (k = d*64+m contiguous in x)
//   U[h,k] = w1*w2 precomputed bf16 hi/lo (Markidis 3-product split)
// mma.sync m16n8k16 bf16 (tcgen05 unavailable: harness targets compute_103, no 'a').

static constexpr int Ddim = 2048;
static constexpr int Mhist = 64;
static constexpr int Hdim = 128;
static constexpr int KTOT = Ddim * Mhist;     // 131072
static constexpr int KC = 64;                  // K per chunk
static constexpr int NCHUNK = KTOT / KC;       // 2048
static constexpr int KSPLIT = 74;              // grid.x ; grid.y = 2 -> 148 CTAs

__device__ __nv_bfloat16 g_U_hi[(size_t)Hdim * KTOT];
__device__ __nv_bfloat16 g_U_lo[(size_t)Hdim * KTOT];
__device__ float g_C[Hdim];

__device__ __forceinline__ uint32_t smem_u32(const void* p) {
    uint32_t a;
    asm("{ .reg .u64 t; cvta.to.shared.u64 t, %1; cvt.u32.u64 %0, t; }" : "=r"(a) : "l"(p));
    return a;
}
__device__ __forceinline__ uint32_t sw128(uint32_t off) { return off ^ ((off >> 3) & 0x70); }
__device__ __forceinline__ uint32_t bf2_bits(__nv_bfloat162 v) {
    return reinterpret_cast<uint32_t&>(v);
}
__device__ __forceinline__ void ldsm_x4(uint32_t& r0, uint32_t& r1, uint32_t& r2, uint32_t& r3,
                                        uint32_t addr) {
    asm volatile("ldmatrix.sync.aligned.m8n8.x4.shared.b16 {%0,%1,%2,%3}, [%4];"
                 : "=r"(r0), "=r"(r1), "=r"(r2), "=r"(r3) : "r"(addr));
}
__device__ __forceinline__ void mma16816(float* c, const uint32_t* a, const uint32_t* b) {
    asm volatile(
        "mma.sync.aligned.m16n8k16.row.col.f32.bf16.bf16.f32 "
        "{%0,%1,%2,%3}, {%4,%5,%6,%7}, {%8,%9}, {%0,%1,%2,%3};"
        : "+f"(c[0]), "+f"(c[1]), "+f"(c[2]), "+f"(c[3])
        : "r"(a[0]), "r"(a[1]), "r"(a[2]), "r"(a[3]), "r"(b[0]), "r"(b[1]));
}
__device__ __forceinline__ void cp_async16(uint32_t dst, const void* src) {
    asm volatile("cp.async.cg.shared.global [%0], [%1], 16;" :: "r"(dst), "l"(src));
}
#define CP_COMMIT() asm volatile("cp.async.commit_group;" ::: "memory")
#define CP_WAIT_ALL() asm volatile("cp.async.wait_group 0;" ::: "memory")

// ---------------- precompute ----------------
// U[h][d*64+m] = w1[(m*128+h)*2048+d] * w2[h*2048+d], bf16 hi/lo split.
// Warp-local smem transpose so every STG is a coalesced 128B line.
__global__ void build_u_kernel(const float* __restrict__ w1, const float* __restrict__ w2) {
    __shared__ uint32_t st[8][33 * 32];           // 33.8KB, stride-33 pad
    int g = blockIdx.x * blockDim.x + threadIdx.x; // 0 .. 128*2048-1
    int w = threadIdx.x >> 5;
    int lane = threadIdx.x & 31;
    int h = g >> 11;
    int d = g & 2047;
    float s = w2[h * Ddim + d];
    uint32_t hi[32], lo[32];
#pragma unroll 16
    for (int m = 0; m < Mhist; m += 2) {
        float a = w1[((size_t)m * Hdim + h) * Ddim + d] * s;
        float b = w1[((size_t)(m + 1) * Hdim + h) * Ddim + d] * s;
        __nv_bfloat162 H = __floats2bfloat162_rn(a, b);
        float la = a - __low2float(H);
        float lb = b - __high2float(H);
        __nv_bfloat162 L = __floats2bfloat162_rn(la, lb);
        hi[m >> 1] = bf2_bits(H);
        lo[m >> 1] = bf2_bits(L);
    }
    // warp covers 32 consecutive d at fixed h -> 4KB contiguous per buffer
    int d0 = d & ~31;
    size_t W0 = (size_t)h * (KTOT / 2) + (size_t)d0 * 32;  // in uint32 words
    uint32_t* oh = reinterpret_cast<uint32_t*>(g_U_hi) + W0;
    uint32_t* ol = reinterpret_cast<uint32_t*>(g_U_lo) + W0;
#pragma unroll
    for (int j = 0; j < 32; j++) st[w][lane * 33 + j] = hi[j];
    __syncwarp();
#pragma unroll
    for (int i = 0; i < 32; i++) oh[i * 32 + lane] = st[w][i * 33 + lane];
    __syncwarp();
#pragma unroll
    for (int j = 0; j < 32; j++) st[w][lane * 33 + j] = lo[j];
    __syncwarp();
#pragma unroll
    for (int i = 0; i < 32; i++) ol[i * 32 + lane] = st[w][i * 33 + lane];
}

// C[h] = sum_d b1[h,d]*w2[h,d] + b2[h]; also initializes out[b,h] = C[h].
__global__ void bias_kernel(const float* __restrict__ b1, const float* __restrict__ w2,
                            const float* __restrict__ b2, float* __restrict__ out) {
    __shared__ float red[256];
    int h = blockIdx.x;
    float s = 0.0f;
    for (int d = threadIdx.x; d < Ddim; d += 256)
        s += b1[h * Ddim + d] * w2[h * Ddim + d];
    red[threadIdx.x] = s;
    __syncthreads();
    for (int st = 128; st > 0; st >>= 1) {
        if (threadIdx.x < st) red[threadIdx.x] += red[threadIdx.x + st];
        __syncthreads();
    }
    __syncthreads();
    float C = red[0] + b2[h];
    out[(size_t)threadIdx.x * Hdim + h] = C;   // 256 rows
    if (threadIdx.x == 0) g_C[h] = C;
}

// ---------------- GEMM ----------------
// 512 threads = 16 warps (4x4), CTA tile 128x128, warp tile 32x32.
// Double-buffered smem: stage = {A_hi, A_lo, B_hi, B_lo} 16KB each = 64KB; 2 stages.
static constexpr int S_AHI = 0;
static constexpr int S_ALO = 16384;
static constexpr int S_BHI = 32768;
static constexpr int S_BLO = 49152;
static constexpr int STAGE = 65536;
static constexpr int SMEM_TOTAL = 2 * STAGE;   // 131072

__global__ void __launch_bounds__(512, 1)
gemm_kernel(const float* __restrict__ x, float* __restrict__ out) {
    extern __shared__ char smem[];
    uint32_t sb = smem_u32(smem);
    int tid = threadIdx.x;
    int wid = tid >> 5;
    int lane = tid & 31;
    int warp_m = wid >> 2;          // 0..3 (32 rows each)
    int warp_n = wid & 3;           // 0..3 (32 cols each)
    int ksp = blockIdx.x;
    int mtile = blockIdx.y;

    int c0 = (ksp * NCHUNK) / KSPLIT;
    int c1 = ((ksp + 1) * NCHUNK) / KSPLIT;

    // loader mapping: row = tid>>2 (0..127), seg = tid&3 (16-elem segment)
    int arow = tid >> 2;
    int seg = tid & 3;
    const float* xr = x + ((size_t)(mtile * 128 + arow)) * KTOT + seg * 16;
    const __nv_bfloat16* uh = g_U_hi + (size_t)arow * KTOT + seg * 16;
    const __nv_bfloat16* ul = g_U_lo + (size_t)arow * KTOT + seg * 16;

    // swizzled smem offsets for this thread's 32B slice (two 16B halves)
    uint32_t o0 = sw128((uint32_t)(arow * 128 + seg * 32));
    uint32_t o1 = sw128((uint32_t)(arow * 128 + seg * 32 + 16));

    // ldmatrix lane address components
    uint32_t a_row_l = (uint32_t)(warp_m * 32 + (lane & 15));
    uint32_t a_kb_l = (uint32_t)((lane >> 4) * 16);
    uint32_t b_row_l = (uint32_t)(warp_n * 32 + ((lane >> 4) << 3) + (lane & 7));
    uint32_t b_kb_l = (uint32_t)(((lane >> 3) & 1) * 16);

    float acc[2][4][4];
#pragma unroll
    for (int i = 0; i < 2; i++)
#pragma unroll
        for (int j = 0; j < 4; j++)
#pragma unroll
            for (int r = 0; r < 4; r++) acc[i][j][r] = 0.0f;

    float4 xreg[4];

    // ---- prologue: chunk c0 ----
    {
        const float4* xp = reinterpret_cast<const float4*>(xr + c0 * KC);
#pragma unroll
        for (int j = 0; j < 4; j++) xreg[j] = xp[j];
        const __nv_bfloat16* uhp = uh + c0 * KC;
        const __nv_bfloat16* ulp = ul + c0 * KC;
        cp_async16(sb + S_BHI + o0, uhp);
        cp_async16(sb + S_BHI + o1, uhp + 8);
        cp_async16(sb + S_BLO + o0, ulp);
        cp_async16(sb + S_BLO + o1, ulp + 8);
        CP_COMMIT();
    }

    for (int c = c0; c < c1; c++) {
        uint32_t stg = (uint32_t)((c - c0) & 1) * STAGE;
        uint32_t nstg = stg ^ STAGE;

        // convert + store A(c): 16 floats -> 16 bf16 hi + 16 bf16 lo (32B each)
        uint2 sh[2], sl[2];
#pragma unroll
        for (int j = 0; j < 4; j++) {
            float4 v = xreg[j];
            __nv_bfloat162 H01 = __floats2bfloat162_rn(v.x, v.y);
            __nv_bfloat162 H23 = __floats2bfloat162_rn(v.z, v.w);
            __nv_bfloat162 L01 = __floats2bfloat162_rn(v.x - __low2float(H01), v.y - __high2float(H01));
            __nv_bfloat162 L23 = __floats2bfloat162_rn(v.z - __low2float(H23), v.w - __high2float(H23));
            sh[j >> 1].x = (j & 1) ? sh[j >> 1].x : bf2_bits(H01);
            // (filled explicitly below to keep vector stores)
            if ((j & 1) == 0) { sh[j >> 1].x = bf2_bits(H01); sh[j >> 1].y = bf2_bits(H23);
                                sl[j >> 1].x = bf2_bits(L01); sl[j >> 1].y = bf2_bits(L23); }
            else {
                uint2 th; th.x = bf2_bits(H01); th.y = bf2_bits(H23);
                uint2 tl; tl.x = bf2_bits(L01); tl.y = bf2_bits(L23);
                // store 16B = {prev 8B, this 8B}
                uint4 vh; vh.x = sh[j >> 1].x; vh.y = sh[j >> 1].y; vh.z = th.x; vh.w = th.y;
                uint4 vl; vl.x = sl[j >> 1].x; vl.y = sl[j >> 1].y; vl.z = tl.x; vl.w = tl.y;
                uint32_t off = (j >> 1) ? o1 : o0;
                *reinterpret_cast<uint4*>(smem + stg + S_AHI + off) = vh;
                *reinterpret_cast<uint4*>(smem + stg + S_ALO + off) = vl;
            }
        }
        CP_WAIT_ALL();           // B(c) landed
        __syncthreads();         // stage(c) visible; stage(c^1) readers done

        if (c + 1 < c1) {
            const float4* xp = reinterpret_cast<const float4*>(xr + (c + 1) * KC);
#pragma unroll
            for (int j = 0; j < 4; j++) xreg[j] = xp[j];
            const __nv_bfloat16* uhp = uh + (c + 1) * KC;
            const __nv_bfloat16* ulp = ul + (c + 1) * KC;
            cp_async16(sb + nstg + S_BHI + o0, uhp);
            cp_async16(sb + nstg + S_BHI + o1, uhp + 8);
            cp_async16(sb + nstg + S_BLO + o0, ulp);
            cp_async16(sb + nstg + S_BLO + o1, ulp + 8);
            CP_COMMIT();
        }

        // ---- MMA on stage(c) ----
        uint32_t Ahi = sb + stg + S_AHI, Alo = sb + stg + S_ALO;
        uint32_t Bhi = sb + stg + S_BHI, Blo = sb + stg + S_BLO;
#pragma unroll
        for (int ks = 0; ks < 4; ks++) {
            uint32_t boff0 = sw128(b_row_l * 128 + ks * 32 + b_kb_l);
            uint32_t boff1 = sw128((b_row_l + 16) * 128 + ks * 32 + b_kb_l);
            uint32_t aoff0 = sw128(a_row_l * 128 + ks * 32 + a_kb_l);
            uint32_t aoff1 = sw128((a_row_l + 16) * 128 + ks * 32 + a_kb_l);
            uint32_t bh[4][2], bl[4][2], ah[2][4], al[2][4];
            ldsm_x4(bh[0][0], bh[0][1], bh[1][0], bh[1][1], Bhi + boff0);
            ldsm_x4(bh[2][0], bh[2][1], bh[3][0], bh[3][1], Bhi + boff1);
            ldsm_x4(ah[0][0], ah[0][1], ah[0][2], ah[0][3], Ahi + aoff0);
            ldsm_x4(ah[1][0], ah[1][1], ah[1][2], ah[1][3], Ahi + aoff1);
#pragma unroll
            for (int mf = 0; mf < 2; mf++)
#pragma unroll
                for (int nf = 0; nf < 4; nf++)
                    mma16816(acc[mf][nf], ah[mf], bh[nf]);      // hi*hi
            ldsm_x4(bl[0][0], bl[0][1], bl[1][0], bl[1][1], Blo + boff0);
            ldsm_x4(bl[2][0], bl[2][1], bl[3][0], bl[3][1], Blo + boff1);
#pragma unroll
            for (int mf = 0; mf < 2; mf++)
#pragma unroll
                for (int nf = 0; nf < 4; nf++)
                    mma16816(acc[mf][nf], ah[mf], bl[nf]);      // hi*lo
            ldsm_x4(al[0][0], al[0][1], al[0][2], al[0][3], Alo + aoff0);
            ldsm_x4(al[1][0], al[1][1], al[1][2], al[1][3], Alo + aoff1);
#pragma unroll
            for (int mf = 0; mf < 2; mf++)
#pragma unroll
                for (int nf = 0; nf < 4; nf++)
                    mma16816(acc[mf][nf], al[mf], bh[nf]);      // lo*hi
        }
    }

    // ---- epilogue: split-K reduce via atomics (out pre-filled with bias) ----
    int r0 = mtile * 128 + warp_m * 32 + (lane >> 2);
    int cc0 = warp_n * 32 + (lane & 3) * 2;
#pragma unroll
    for (int mf = 0; mf < 2; mf++) {
#pragma unroll
        for (int nf = 0; nf < 4; nf++) {
            int row = r0 + mf * 16;
            int col = cc0 + nf * 8;
            atomicAdd(out + (size_t)row * Hdim + col,           acc[mf][nf][0]);
            atomicAdd(out + (size_t)row * Hdim + col + 1,       acc[mf][nf][1]);
            atomicAdd(out + (size_t)(row + 8) * Hdim + col,     acc[mf][nf][2]);
            atomicAdd(out + (size_t)(row + 8) * Hdim + col + 1, acc[mf][nf][3]);
        }
    }
}

// ---------------- launch ----------------
extern "C" void kernel_launch(void* const* d_in, const int* in_sizes, int n_in,
                              void* d_out, int out_size) {
    const float* x  = (const float*)d_in[0];
    const float* w1 = (const float*)d_in[1];
    const float* b1 = (const float*)d_in[2];
    const float* w2 = (const float*)d_in[3];
    const float* b2 = (const float*)d_in[4];
    float* out = (float*)d_out;

    cudaFuncSetAttribute(gemm_kernel, cudaFuncAttributeMaxDynamicSharedMemorySize, SMEM_TOTAL);

    build_u_kernel<<<(Hdim * Ddim) / 256, 256>>>(w1, w2);
    bias_kernel<<<Hdim, 256>>>(b1, w2, b2, out);
    dim3 grid(KSPLIT, 2);
    gemm_kernel<<<grid, 512, SMEM_TOTAL>>>(x, out);
}

// round 5
// speedup vs baseline: 1.9520x; 1.0931x over previous
#include <cuda_runtime.h>
#include <cuda_fp16.h>
#include <cstdint>

// out[b,h] = sum_{d,m} x[b,d,m]*w1[m,h,d]*w2[h,d] + C[h]
//   -> one GEMM: M=256, N=128, K=131072 (k = d*64+m contiguous in x)
//   U[h,k] = w1*w2*256 precomputed as SINGLE fp16 (scaled; error 2^-11 -> ~3e-4)
//   x split exactly into fp16 hi+lo  ->  out = (xh*U + xl*U)/256  : 2 MMA products
// mma.sync m16n8k16 f16 (tcgen05 unavailable: harness targets compute_103, no 'a').

static constexpr int Ddim = 2048;
static constexpr int Mhist = 64;
static constexpr int Hdim = 128;
static constexpr int KTOT = Ddim * Mhist;     // 131072
static constexpr int KC = 64;                  // K per chunk
static constexpr int NCHUNK = KTOT / KC;       // 2048
static constexpr int KSPLIT = 74;              // grid.x ; grid.y = 2 -> 148 CTAs
static constexpr float USCALE = 256.0f;
static constexpr float UINV = 1.0f / 256.0f;

__device__ __half g_U[(size_t)Hdim * KTOT];    // 32 MB, L2-resident
__device__ float g_C[Hdim];

__device__ __forceinline__ uint32_t smem_u32(const void* p) {
    uint32_t a;
    asm("{ .reg .u64 t; cvta.to.shared.u64 t, %1; cvt.u32.u64 %0, t; }" : "=r"(a) : "l"(p));
    return a;
}
__device__ __forceinline__ uint32_t sw128(uint32_t off) { return off ^ ((off >> 3) & 0x70); }
__device__ __forceinline__ uint32_t h2_bits(__half2 v) {
    return reinterpret_cast<uint32_t&>(v);
}
__device__ __forceinline__ void ldsm_x4(uint32_t& r0, uint32_t& r1, uint32_t& r2, uint32_t& r3,
                                        uint32_t addr) {
    asm volatile("ldmatrix.sync.aligned.m8n8.x4.shared.b16 {%0,%1,%2,%3}, [%4];"
                 : "=r"(r0), "=r"(r1), "=r"(r2), "=r"(r3) : "r"(addr));
}
__device__ __forceinline__ void mma16816(float* c, const uint32_t* a, const uint32_t* b) {
    asm volatile(
        "mma.sync.aligned.m16n8k16.row.col.f32.f16.f16.f32 "
        "{%0,%1,%2,%3}, {%4,%5,%6,%7}, {%8,%9}, {%0,%1,%2,%3};"
        : "+f"(c[0]), "+f"(c[1]), "+f"(c[2]), "+f"(c[3])
        : "r"(a[0]), "r"(a[1]), "r"(a[2]), "r"(a[3]), "r"(b[0]), "r"(b[1]));
}
__device__ __forceinline__ void cp_async16(uint32_t dst, const void* src) {
    asm volatile("cp.async.cg.shared.global [%0], [%1], 16;" :: "r"(dst), "l"(src));
}
#define CP_COMMIT() asm volatile("cp.async.commit_group;" ::: "memory")
#define CP_WAIT_ALL() asm volatile("cp.async.wait_group 0;" ::: "memory")

// ---------------- precompute ----------------
// U[h][d*64+m] = w1[(m*128+h)*2048+d] * w2[h*2048+d] * 256, fp16.
// Warp-local smem transpose -> coalesced 4KB-per-warp STG.
__global__ void build_u_kernel(const float* __restrict__ w1, const float* __restrict__ w2) {
    __shared__ uint32_t st[8][33 * 32];
    int g = blockIdx.x * blockDim.x + threadIdx.x;  // 0 .. 128*2048-1
    int w = threadIdx.x >> 5;
    int lane = threadIdx.x & 31;
    int h = g >> 11;
    int d = g & 2047;
    float s = w2[h * Ddim + d] * USCALE;
    uint32_t uu[32];
#pragma unroll 16
    for (int m = 0; m < Mhist; m += 2) {
        float a = w1[((size_t)m * Hdim + h) * Ddim + d] * s;
        float b = w1[((size_t)(m + 1) * Hdim + h) * Ddim + d] * s;
        uu[m >> 1] = h2_bits(__floats2half2_rn(a, b));
    }
    // words: W = h*65536 + d*32 + j ; warp covers d in [d0,d0+32) -> 4KB contiguous
    int d0 = d & ~31;
    uint32_t* ou = reinterpret_cast<uint32_t*>(g_U) + (size_t)h * (KTOT / 2) + (size_t)d0 * 32;
#pragma unroll
    for (int j = 0; j < 32; j++) st[w][lane * 33 + j] = uu[j];
    __syncwarp();
#pragma unroll
    for (int i = 0; i < 32; i++) ou[i * 32 + lane] = st[w][i * 33 + lane];
}

// C[h] = sum_d b1[h,d]*w2[h,d] + b2[h]; also initializes out[b,h] = C[h].
__global__ void bias_kernel(const float* __restrict__ b1, const float* __restrict__ w2,
                            const float* __restrict__ b2, float* __restrict__ out) {
    __shared__ float red[256];
    int h = blockIdx.x;
    float s = 0.0f;
    for (int d = threadIdx.x; d < Ddim; d += 256)
        s += b1[h * Ddim + d] * w2[h * Ddim + d];
    red[threadIdx.x] = s;
    __syncthreads();
    for (int st = 128; st > 0; st >>= 1) {
        if (threadIdx.x < st) red[threadIdx.x] += red[threadIdx.x + st];
        __syncthreads();
    }
    __syncthreads();
    float C = red[0] + b2[h];
    out[(size_t)threadIdx.x * Hdim + h] = C;   // 256 rows
    if (threadIdx.x == 0) g_C[h] = C;
}

// ---------------- GEMM ----------------
// 512 threads = 16 warps (4x4), CTA tile 128x128, warp tile 32x32.
// stage = {A_hi 16K, A_lo 16K, B 16K} = 48KB; 2 stages = 96KB.
static constexpr int S_AHI = 0;
static constexpr int S_ALO = 16384;
static constexpr int S_B = 32768;
static constexpr int STAGE = 49152;
static constexpr int SMEM_TOTAL = 2 * STAGE;   // 98304

// convert 16 fp32 -> 16 fp16 hi + 16 fp16 lo, store 2x16B to each A buffer
__device__ __forceinline__ void sts_A(char* smem, uint32_t stg, const float4* v,
                                      uint32_t o0, uint32_t o1) {
    uint32_t h[8], l[8];
#pragma unroll
    for (int j = 0; j < 4; j++) {
        float4 t = v[j];
        __half2 H01 = __floats2half2_rn(t.x, t.y);
        float2 b01 = __half22float2(H01);
        __half2 L01 = __floats2half2_rn(t.x - b01.x, t.y - b01.y);
        __half2 H23 = __floats2half2_rn(t.z, t.w);
        float2 b23 = __half22float2(H23);
        __half2 L23 = __floats2half2_rn(t.z - b23.x, t.w - b23.y);
        h[2 * j] = h2_bits(H01); h[2 * j + 1] = h2_bits(H23);
        l[2 * j] = h2_bits(L01); l[2 * j + 1] = h2_bits(L23);
    }
    uint4 vh0; vh0.x = h[0]; vh0.y = h[1]; vh0.z = h[2]; vh0.w = h[3];
    uint4 vh1; vh1.x = h[4]; vh1.y = h[5]; vh1.z = h[6]; vh1.w = h[7];
    uint4 vl0; vl0.x = l[0]; vl0.y = l[1]; vl0.z = l[2]; vl0.w = l[3];
    uint4 vl1; vl1.x = l[4]; vl1.y = l[5]; vl1.z = l[6]; vl1.w = l[7];
    *reinterpret_cast<uint4*>(smem + stg + S_AHI + o0) = vh0;
    *reinterpret_cast<uint4*>(smem + stg + S_AHI + o1) = vh1;
    *reinterpret_cast<uint4*>(smem + stg + S_ALO + o0) = vl0;
    *reinterpret_cast<uint4*>(smem + stg + S_ALO + o1) = vl1;
}

__global__ void __launch_bounds__(512, 1)
gemm_kernel(const float* __restrict__ x, float* __restrict__ out) {
    extern __shared__ char smem[];
    uint32_t sb = smem_u32(smem);
    int tid = threadIdx.x;
    int wid = tid >> 5;
    int lane = tid & 31;
    int warp_m = wid >> 2;
    int warp_n = wid & 3;
    int ksp = blockIdx.x;
    int mtile = blockIdx.y;

    int c0 = (ksp * NCHUNK) / KSPLIT;
    int c1 = ((ksp + 1) * NCHUNK) / KSPLIT;

    int arow = tid >> 2;
    int seg = tid & 3;
    const float* xr = x + ((size_t)(mtile * 128 + arow)) * KTOT + seg * 16;
    const __half* ub = g_U + (size_t)arow * KTOT + seg * 16;

    uint32_t o0 = sw128((uint32_t)(arow * 128 + seg * 32));
    uint32_t o1 = sw128((uint32_t)(arow * 128 + seg * 32 + 16));

    uint32_t a_row_l = (uint32_t)(warp_m * 32 + (lane & 15));
    uint32_t a_kb_l = (uint32_t)((lane >> 4) * 16);
    uint32_t b_row_l = (uint32_t)(warp_n * 32 + ((lane >> 4) << 3) + (lane & 7));
    uint32_t b_kb_l = (uint32_t)(((lane >> 3) & 1) * 16);

    float acc[2][4][4];
#pragma unroll
    for (int i = 0; i < 2; i++)
#pragma unroll
        for (int j = 0; j < 4; j++)
#pragma unroll
            for (int r = 0; r < 4; r++) acc[i][j][r] = 0.0f;

    float4 xa[4], xb[4];

    // ---- prologue ----
    {
        const float4* xp = reinterpret_cast<const float4*>(xr + c0 * KC);
#pragma unroll
        for (int j = 0; j < 4; j++) xa[j] = xp[j];
        const __half* up = ub + c0 * KC;
        cp_async16(sb + S_B + o0, up);
        cp_async16(sb + S_B + o1, up + 8);
        CP_COMMIT();
        sts_A(smem, 0, xa, o0, o1);                    // A(c0) -> stage0
        if (c0 + 1 < c1) {
            const float4* xq = reinterpret_cast<const float4*>(xr + (c0 + 1) * KC);
#pragma unroll
            for (int j = 0; j < 4; j++) xa[j] = xq[j]; // xa holds x(c0+1)
        }
    }

    for (int c = c0; c < c1; c++) {
        uint32_t stg = (uint32_t)((c - c0) & 1) * STAGE;
        uint32_t nstg = stg ^ STAGE;

        CP_WAIT_ALL();           // B(c) landed
        __syncthreads();         // stage(c) ready; other stage free to write

        if (c + 1 < c1) {
            if (c + 2 < c1) {
                const float4* xp = reinterpret_cast<const float4*>(xr + (c + 2) * KC);
#pragma unroll
                for (int j = 0; j < 4; j++) xb[j] = xp[j];
            }
            const __half* up = ub + (c + 1) * KC;
            cp_async16(sb + nstg + S_B + o0, up);
            cp_async16(sb + nstg + S_B + o1, up + 8);
            CP_COMMIT();
            sts_A(smem, nstg, xa, o0, o1);             // A(c+1), overlapped with MMA(c)
            if (c + 2 < c1) {
#pragma unroll
                for (int j = 0; j < 4; j++) xa[j] = xb[j];
            }
        }

        // ---- MMA on stage(c): 2 products (xh*U, xl*U) ----
        uint32_t Ahi = sb + stg + S_AHI, Alo = sb + stg + S_ALO, Bb = sb + stg + S_B;
#pragma unroll
        for (int ks = 0; ks < 4; ks++) {
            uint32_t boff0 = sw128(b_row_l * 128 + ks * 32 + b_kb_l);
            uint32_t boff1 = sw128((b_row_l + 16) * 128 + ks * 32 + b_kb_l);
            uint32_t aoff0 = sw128(a_row_l * 128 + ks * 32 + a_kb_l);
            uint32_t aoff1 = sw128((a_row_l + 16) * 128 + ks * 32 + a_kb_l);
            uint32_t bh[4][2], ah[2][4], al[2][4];
            ldsm_x4(bh[0][0], bh[0][1], bh[1][0], bh[1][1], Bb + boff0);
            ldsm_x4(bh[2][0], bh[2][1], bh[3][0], bh[3][1], Bb + boff1);
            ldsm_x4(ah[0][0], ah[0][1], ah[0][2], ah[0][3], Ahi + aoff0);
            ldsm_x4(ah[1][0], ah[1][1], ah[1][2], ah[1][3], Ahi + aoff1);
#pragma unroll
            for (int mf = 0; mf < 2; mf++)
#pragma unroll
                for (int nf = 0; nf < 4; nf++)
                    mma16816(acc[mf][nf], ah[mf], bh[nf]);      // xh * U
            ldsm_x4(al[0][0], al[0][1], al[0][2], al[0][3], Alo + aoff0);
            ldsm_x4(al[1][0], al[1][1], al[1][2], al[1][3], Alo + aoff1);
#pragma unroll
            for (int mf = 0; mf < 2; mf++)
#pragma unroll
                for (int nf = 0; nf < 4; nf++)
                    mma16816(acc[mf][nf], al[mf], bh[nf]);      // xl * U
        }
    }

    // ---- epilogue: unscale + split-K atomic reduce (out pre-filled with bias) ----
    int r0 = mtile * 128 + warp_m * 32 + (lane >> 2);
    int cc0 = warp_n * 32 + (lane & 3) * 2;
#pragma unroll
    for (int mf = 0; mf < 2; mf++) {
#pragma unroll
        for (int nf = 0; nf < 4; nf++) {
            int row = r0 + mf * 16;
            int col = cc0 + nf * 8;
            atomicAdd(out + (size_t)row * Hdim + col,           acc[mf][nf][0] * UINV);
            atomicAdd(out + (size_t)row * Hdim + col + 1,       acc[mf][nf][1] * UINV);
            atomicAdd(out + (size_t)(row + 8) * Hdim + col,     acc[mf][nf][2] * UINV);
            atomicAdd(out + (size_t)(row + 8) * Hdim + col + 1, acc[mf][nf][3] * UINV);
        }
    }
}

// ---------------- launch ----------------
extern "C" void kernel_launch(void* const* d_in, const int* in_sizes, int n_in,
                              void* d_out, int out_size) {
    const float* x  = (const float*)d_in[0];
    const float* w1 = (const float*)d_in[1];
    const float* b1 = (const float*)d_in[2];
    const float* w2 = (const float*)d_in[3];
    const float* b2 = (const float*)d_in[4];
    float* out = (float*)d_out;

    cudaFuncSetAttribute(gemm_kernel, cudaFuncAttributeMaxDynamicSharedMemorySize, SMEM_TOTAL);

    build_u_kernel<<<(Hdim * Ddim) / 256, 256>>>(w1, w2);
    bias_kernel<<<Hdim, 256>>>(b1, w2, b2, out);
    dim3 grid(KSPLIT, 2);
    gemm_kernel<<<grid, 512, SMEM_TOTAL>>>(x, out);
}